// round 9
// baseline (speedup 1.0000x reference)
#include <cuda_runtime.h>
#include <cstddef>

// Problem shape
#define BATCH 4096
#define FN    1024
#define RC    19
#define RD    1024
#define FLAT  (FN * RC)            // 19456 floats per conv batch row

#define W_SMEM_BYTES (FLAT * 4)    // 77824 B (all of R staged in smem)

__device__ float g_W[FLAT];        // W[f][r] flat, matches conv's [f*19+r]

// ---------------------------------------------------------------------------
// Kernel 1: W = U @ R^T with R staged in shared memory.
// 256 blocks x 128 threads (warp-per-f, 4 f per block): halves per-block LDS
// work vs the 128-block version (~1.3 us). Ends with an explicit PDL trigger
// so the dependent score kernel can launch/setup while this grid drains.
// ---------------------------------------------------------------------------
__global__ void compute_w_kernel(const float* __restrict__ U,
                                 const float* __restrict__ R) {
    extern __shared__ float sR[];
    const int tid  = threadIdx.x;
    const int lane = tid & 31;
    const int wid  = tid >> 5;

    // Stage R: 4864 float4 / 128 threads = 38 each, coalesced.
    {
        float4* s4 = reinterpret_cast<float4*>(sR);
        const float4* g4 = reinterpret_cast<const float4*>(R);
#pragma unroll
        for (int k = 0; k < 38; k++)
            s4[tid + 128 * k] = g4[tid + 128 * k];
    }
    __syncthreads();

    const int f = blockIdx.x * 4 + wid;
    const float4* u4 = reinterpret_cast<const float4*>(U + (size_t)f * RD);
    float4 u[8];
#pragma unroll
    for (int i = 0; i < 8; i++) u[i] = u4[lane + 32 * i];

    for (int r = 0; r < RC; r++) {
        const float4* r4 = reinterpret_cast<const float4*>(sR + (size_t)r * RD);
        float s = 0.f;
#pragma unroll
        for (int i = 0; i < 8; i++) {
            float4 rv = r4[lane + 32 * i];
            s += u[i].x * rv.x + u[i].y * rv.y + u[i].z * rv.z + u[i].w * rv.w;
        }
#pragma unroll
        for (int off = 16; off > 0; off >>= 1)
            s += __shfl_xor_sync(0xffffffffu, s, off);
        if (lane == 0) g_W[f * RC + r] = s;
    }

    // PDL: allow the dependent score kernel's CTAs to launch.
    cudaTriggerProgrammaticLaunchCompletion();
}

// ---------------------------------------------------------------------------
// Kernel 2: score[b][r] = sum_f conv[b][f][r] * W[f][r]
// EXACT r2 hot path (empirically fastest: 54.7 us, 74.4% DRAM):
// warp-per-batch b = blk*8 + wid, 152 unit-stride float4 LDGs (__ldcs) paired
// with L1-resident W (__ldg), rotating compile-time accumulator slots, one
// shuffle butterfly, direct stores. Plus a PDL grid-dependency sync before
// the first g_W read.
//   flat idx = i*128 + 4*lane + j, 128 % 19 = 14:
//   r = (14*i + 4*lane + j) mod 19, slot k = (14*i + j) mod 19.
// ---------------------------------------------------------------------------
__global__ __launch_bounds__(256, 4)
void score_kernel(const float* __restrict__ conv, float* __restrict__ out) {
    const int lane = threadIdx.x & 31;
    const int b    = blockIdx.x * 8 + (threadIdx.x >> 5);   // warp-per-batch

    const float4* c4 = reinterpret_cast<const float4*>(conv + (size_t)b * FLAT);
    const float4* w4 = reinterpret_cast<const float4*>(g_W);

    float acc[RC];
#pragma unroll
    for (int k = 0; k < RC; k++) acc[k] = 0.f;

    // Wait for compute_w's writes to be visible (no-op if PDL not active).
    cudaGridDependencySynchronize();

    // 152 warp-iterations = 8 outer x 19 inner (slot pattern period = 19)
    for (int o = 0; o < 8; o++) {
        const int base = o * (19 * 32) + lane;
#pragma unroll
        for (int t = 0; t < 19; t++) {
            float4 cv = __ldcs(&c4[base + t * 32]);   // streaming, read-once
            float4 wv = __ldg(&w4[base + t * 32]);    // L1-resident
            acc[(14 * t + 0) % RC] += cv.x * wv.x;
            acc[(14 * t + 1) % RC] += cv.y * wv.y;
            acc[(14 * t + 2) % RC] += cv.z * wv.z;
            acc[(14 * t + 3) % RC] += cv.w * wv.w;
        }
    }

    // Butterfly: lane l slot k holds r=(4l+k)%19; peer l+d has it at (k-4d)%19.
#pragma unroll
    for (int d = 16; d >= 1; d >>= 1) {
        float tmp[RC];
#pragma unroll
        for (int k = 0; k < RC; k++) {
            const int s = (k + 4 * RC - 4 * d) % RC;
            tmp[k] = __shfl_down_sync(0xffffffffu, acc[s], d);
        }
#pragma unroll
        for (int k = 0; k < RC; k++) acc[k] += tmp[k];
    }

    // Lane 0: slot k == relation k (r0 = 0). Direct stores, no atomics.
    if (lane == 0) {
        float* ob = out + (size_t)b * RC;
#pragma unroll
        for (int k = 0; k < RC; k++) ob[k] = acc[k];
    }
}

// ---------------------------------------------------------------------------
// Launch: compute_w, then score with PDL so its CTAs launch while compute_w
// drains. Graph-capturable (kernel launches only, default stream).
// ---------------------------------------------------------------------------
extern "C" void kernel_launch(void* const* d_in, const int* in_sizes, int n_in,
                              void* d_out, int out_size) {
    const float* conv = nullptr;
    const float* R    = nullptr;
    const float* U    = nullptr;
    for (int i = 0; i < n_in; i++) {
        long long n = in_sizes[i];
        if (n == (long long)BATCH * FN * RC)      conv = (const float*)d_in[i];
        else if (n == (long long)RC * RD)         R    = (const float*)d_in[i];
        else if (n == (long long)FN * RD)         U    = (const float*)d_in[i];
    }
    float* out = (float*)d_out;

    cudaFuncSetAttribute(compute_w_kernel,
                         cudaFuncAttributeMaxDynamicSharedMemorySize, W_SMEM_BYTES);
    compute_w_kernel<<<256, 128, W_SMEM_BYTES>>>(U, R);

    cudaLaunchConfig_t cfg = {};
    cfg.gridDim  = dim3(512, 1, 1);     // 4096 warps, warp-per-batch
    cfg.blockDim = dim3(256, 1, 1);
    cfg.dynamicSmemBytes = 0;
    cfg.stream = 0;
    cudaLaunchAttribute attr[1];
    attr[0].id = cudaLaunchAttributeProgrammaticStreamSerialization;
    attr[0].val.programmaticStreamSerializationAllowed = 1;
    cfg.attrs = attr;
    cfg.numAttrs = 1;
    cudaLaunchKernelEx(&cfg, score_kernel, conv, out);
}